// round 4
// baseline (speedup 1.0000x reference)
#include <cuda_runtime.h>
#include <stdint.h>

// Problem constants
#define B        8
#define D        256          // 16x16 score grid
#define NSAMP    500
#define KTOP     10
#define SCALE    64
#define PATCH    128
#define IMGH     1024
#define IMGW     1024
#define PATCH_ELEMS (B * KTOP * 3 * PATCH * PATCH)  // 3,932,160

// ------------------------- scratch (static, no allocs) -------------------------
__device__ float g_norm[B * D];
__device__ int   g_count[B * KTOP * D];
__device__ int   g_nzcnt[B * KTOP];
__device__ int2  g_nzcw[B * KTOP * D];   // {packed (rowbase<<16 | colbase&0xFFFF), weight bits}

// ------------------------- threefry2x32 (JAX key(1) = {0,1}) -------------------
__device__ __forceinline__ uint32_t rotl32(uint32_t v, int r) {
    return (v << r) | (v >> (32 - r));
}
__device__ __forceinline__ void tf_round(uint32_t& x0, uint32_t& x1, int r) {
    x0 += x1; x1 = rotl32(x1, r); x1 ^= x0;
}
__device__ __forceinline__ void threefry2x32(uint32_t c0, uint32_t c1,
                                             uint32_t& o0, uint32_t& o1) {
    const uint32_t ks0 = 0u, ks1 = 1u, ks2 = 0x1BD11BDAu ^ ks0 ^ ks1;
    uint32_t x0 = c0 + ks0, x1 = c1 + ks1;
    tf_round(x0, x1, 13); tf_round(x0, x1, 15); tf_round(x0, x1, 26); tf_round(x0, x1, 6);
    x0 += ks1; x1 += ks2 + 1u;
    tf_round(x0, x1, 17); tf_round(x0, x1, 29); tf_round(x0, x1, 16); tf_round(x0, x1, 24);
    x0 += ks2; x1 += ks0 + 2u;
    tf_round(x0, x1, 13); tf_round(x0, x1, 15); tf_round(x0, x1, 26); tf_round(x0, x1, 6);
    x0 += ks0; x1 += ks1 + 3u;
    tf_round(x0, x1, 17); tf_round(x0, x1, 29); tf_round(x0, x1, 16); tf_round(x0, x1, 24);
    x0 += ks1; x1 += ks2 + 4u;
    tf_round(x0, x1, 13); tf_round(x0, x1, 15); tf_round(x0, x1, 26); tf_round(x0, x1, 6);
    x0 += ks2; x1 += ks0 + 5u;
    o0 = x0; o1 = x1;
}

// XLA ErfInv32 (Giles) — exact coefficients XLA emits for lax.erf_inv on f32
__device__ __forceinline__ float erfinv_xla(float x) {
    float w = -log1pf(-__fmul_rn(x, x));
    float p;
    if (w < 5.0f) {
        w = w - 2.5f;
        p = 2.81022636e-08f;
        p = fmaf(p, w, 3.43273939e-07f);
        p = fmaf(p, w, -3.5233877e-06f);
        p = fmaf(p, w, -4.39150654e-06f);
        p = fmaf(p, w, 0.00021858087f);
        p = fmaf(p, w, -0.00125372503f);
        p = fmaf(p, w, -0.00417768164f);
        p = fmaf(p, w, 0.246640727f);
        p = fmaf(p, w, 1.50140941f);
    } else {
        w = sqrtf(w) - 3.0f;
        p = -0.000200214257f;
        p = fmaf(p, w, 0.000100950558f);
        p = fmaf(p, w, 0.00134934322f);
        p = fmaf(p, w, -0.00367342844f);
        p = fmaf(p, w, 0.00573950773f);
        p = fmaf(p, w, -0.0076224613f);
        p = fmaf(p, w, 0.00943887047f);
        p = fmaf(p, w, 1.00167406f);
        p = fmaf(p, w, 2.83297682f);
    }
    return __fmul_rn(p, x);
}

// noise[e] exactly as jax.random.normal(key(1), (8,500,256), f32) with
// jax_threefry_partitionable=True: counter=(0,e), bits = o0 ^ o1
__device__ __forceinline__ float jax_normal(uint32_t e) {
    uint32_t o0, o1;
    threefry2x32(0u, e, o0, o1);
    uint32_t bits = o0 ^ o1;
    float u = __uint_as_float((bits >> 9) | 0x3f800000u) - 1.0f;  // [0,1)
    const float lo = -0.99999994f;            // nextafter(-1,0) in f32
    const float span = 2.0f;                  // f32(1.0 - lo)
    float v = fmaxf(lo, __fadd_rn(__fmul_rn(u, span), lo));
    return __fmul_rn(1.41421354f /* f32(sqrt(2)) */, erfinv_xla(v));
}

// ------------------------- kernel 1: entropy + normalize + zero counts ---------
__global__ void k1_prep(const float* __restrict__ scores, float* __restrict__ entr_out) {
    int tid = threadIdx.x;
    for (int i = tid; i < B * KTOP * D; i += 256) g_count[i] = 0;

    int w = tid >> 5;        // warp = batch
    int lane = tid & 31;
    const float* s = scores + w * D;

    float v[8];
    float mx = -3.0e38f, mn = 3.0e38f;
    #pragma unroll
    for (int q = 0; q < 8; q++) {
        v[q] = s[lane + q * 32];
        mx = fmaxf(mx, v[q]);
        mn = fminf(mn, v[q]);
    }
    #pragma unroll
    for (int o = 16; o; o >>= 1) {
        mx = fmaxf(mx, __shfl_xor_sync(0xffffffffu, mx, o));
        mn = fminf(mn, __shfl_xor_sync(0xffffffffu, mn, o));
    }
    float sumexp = 0.f;
    #pragma unroll
    for (int q = 0; q < 8; q++) sumexp += expf(v[q] - mx);
    #pragma unroll
    for (int o = 16; o; o >>= 1) sumexp += __shfl_xor_sync(0xffffffffu, sumexp, o);
    float lse = mx + logf(sumexp);

    float ent = 0.f;
    #pragma unroll
    for (int q = 0; q < 8; q++) {
        float lp = v[q] - lse;
        ent += expf(lp) * (-lp);
    }
    #pragma unroll
    for (int o = 16; o; o >>= 1) ent += __shfl_xor_sync(0xffffffffu, ent, o);

    float denom = (mx - mn) + 1e-05f;
    #pragma unroll
    for (int q = 0; q < 8; q++)
        g_norm[w * D + lane + q * 32] = __fdiv_rn(v[q] - mn, denom);

    __shared__ float sh_ent[8];
    if (lane == 0) sh_ent[w] = ent;
    __syncthreads();
    if (tid == 0) {
        float e = 0.f;
        #pragma unroll
        for (int i = 0; i < 8; i++) e += sh_ent[i];
        *entr_out = e * (1.0f / 8.0f);
    }
}

// ------------------------- kernel 2: warp-per-sample top-10 --------------------
// 500 blocks x 256 threads; each warp handles one sample, no barriers.
#define SWAPD(i, j) { if (key[i] < key[j]) { unsigned long long t = key[i]; key[i] = key[j]; key[j] = t; } }

__global__ void k2_topk() {
    int wid = threadIdx.x >> 5, lane = threadIdx.x & 31;
    int bs = blockIdx.x * 8 + wid;          // 0..3999
    int b = bs / NSAMP;

    unsigned long long key[8];
    #pragma unroll
    for (int q = 0; q < 8; q++) {
        int j = q * 32 + lane;
        float noise = jax_normal((uint32_t)bs * D + (uint32_t)j);
        float pert = __fadd_rn(g_norm[b * D + j], __fmul_rn(noise, 0.05f));
        uint32_t fb = __float_as_uint(pert);
        uint32_t ordv = fb ^ ((fb & 0x80000000u) ? 0xFFFFFFFFu : 0x80000000u);
        key[q] = ((unsigned long long)ordv << 8) | (unsigned long long)(255 - j);
    }

    // sort key[0..7] descending (19-comparator network)
    SWAPD(0,1) SWAPD(2,3) SWAPD(4,5) SWAPD(6,7)
    SWAPD(0,2) SWAPD(1,3) SWAPD(4,6) SWAPD(5,7)
    SWAPD(1,2) SWAPD(5,6)
    SWAPD(0,4) SWAPD(1,5) SWAPD(2,6) SWAPD(3,7)
    SWAPD(2,4) SWAPD(3,5)
    SWAPD(1,2) SWAPD(3,4) SWAPD(5,6)

    // 10 selection rounds; round t's winner index is kept by lane t only.
    int mine = -1;
    #pragma unroll
    for (int t = 0; t < KTOP; t++) {
        uint32_t kv = (uint32_t)(key[0] >> 8);        // ordv of my head
        uint32_t kj = (uint32_t)key[0] & 0xFFu;       // 255 - j
        uint32_t m1 = __reduce_max_sync(0xffffffffu, kv);
        uint32_t cand = (kv == m1) ? kj : 0u;
        uint32_t m2 = __reduce_max_sync(0xffffffffu, cand);
        if (lane == t) mine = 255 - (int)m2;
        if (kv == m1 && kj == m2) {                   // unique lane: pop my head
            #pragma unroll
            for (int i = 0; i < 7; i++) key[i] = key[i + 1];
            key[7] = 0ull;
        }
    }

    // ascending rank of each winner among the 10 (indices are distinct)
    int rank = 0;
    #pragma unroll
    for (int o = 0; o < KTOP; o++) {
        int other = __shfl_sync(0xffffffffu, mine, o);
        rank += (other < mine);                        // mine=-1 on lanes>=10: harmless
    }
    if (lane < KTOP)
        atomicAdd(&g_count[(b * KTOP + rank) * D + mine], 1);
}

// ------------------------- kernel 3: compact nonzero weights -------------------
__global__ void k3_compact() {
    int bk = blockIdx.x;            // 0..79
    __shared__ int cnt;
    if (threadIdx.x == 0) cnt = 0;
    __syncthreads();
    int c = g_count[bk * D + threadIdx.x];
    if (c > 0) {
        int p = atomicAdd(&cnt, 1);
        int cell = threadIdx.x;
        int rowb = (cell >> 4) * SCALE - 32;           // [-32, 928]
        int colb = (cell & 15) * SCALE - 32;           // [-32, 928]
        g_nzcw[bk * D + p] = make_int2((rowb << 16) | (colb & 0xFFFF),
                                       __float_as_int((float)c / 500.0f));
    }
    __syncthreads();
    if (threadIdx.x == 0) g_nzcnt[bk] = cnt;
}

// ------------------------- kernel 4: sparse patch gather -----------------------
// grid (80, 12): x = b*10+k, y = c*4 + rowtile(32 rows)
// block 256: lanes -> 4 w-pixels; warp id -> row base; 4 rows per thread.
// m-loop unrolled x2 with masked (select) loads so 8 LDG.128 are in flight.
__global__ void k4_patches(const float* __restrict__ x, float* __restrict__ out) {
    int bk = blockIdx.x;
    int b = bk / KTOP;
    int cz = blockIdx.y;
    int c = cz >> 2, tile = cz & 3;

    __shared__ int2 scw[D];
    int nnz = g_nzcnt[bk];
    if (threadIdx.x < nnz)
        scw[threadIdx.x] = g_nzcw[bk * D + threadIdx.x];
    __syncthreads();

    const float* plane = x + ((size_t)(b * 3 + c) << 20);   // 1024*1024 per plane
    float* obase = out + ((size_t)(bk * 3 + c) << 14);      // 128*128 per (b,k,c)

    int w0 = (threadIdx.x & 31) * 4;        // 0..124
    int hbase = tile * 32 + (threadIdx.x >> 5);

    float4 acc0 = make_float4(0.f, 0.f, 0.f, 0.f);
    float4 acc1 = acc0, acc2 = acc0, acc3 = acc0;
    const float4 f4z = make_float4(0.f, 0.f, 0.f, 0.f);

    #define LOADC(cw, V0, V1, V2, V3, WT)                                          \
        {                                                                          \
            int rowb = (cw).x >> 16;                                               \
            int colb = ((cw).x << 16) >> 16;                                       \
            WT = __int_as_float((cw).y);                                           \
            int cc = colb + w0;                                                    \
            bool vc = (unsigned)cc < (unsigned)IMGW;                               \
            int rr = rowb + hbase;                                                 \
            const float* p = plane + rr * IMGW + cc;                               \
            V0 = (vc && (unsigned)(rr)        < (unsigned)IMGH) ? *(const float4*)(p)         : f4z; \
            V1 = (vc && (unsigned)(rr + 8)    < (unsigned)IMGH) ? *(const float4*)(p + 8192)  : f4z; \
            V2 = (vc && (unsigned)(rr + 16)   < (unsigned)IMGH) ? *(const float4*)(p + 16384) : f4z; \
            V3 = (vc && (unsigned)(rr + 24)   < (unsigned)IMGH) ? *(const float4*)(p + 24576) : f4z; \
        }
    #define ACC4(V0, V1, V2, V3, WT)                                   \
        acc0.x = fmaf(WT, V0.x, acc0.x); acc0.y = fmaf(WT, V0.y, acc0.y); \
        acc0.z = fmaf(WT, V0.z, acc0.z); acc0.w = fmaf(WT, V0.w, acc0.w); \
        acc1.x = fmaf(WT, V1.x, acc1.x); acc1.y = fmaf(WT, V1.y, acc1.y); \
        acc1.z = fmaf(WT, V1.z, acc1.z); acc1.w = fmaf(WT, V1.w, acc1.w); \
        acc2.x = fmaf(WT, V2.x, acc2.x); acc2.y = fmaf(WT, V2.y, acc2.y); \
        acc2.z = fmaf(WT, V2.z, acc2.z); acc2.w = fmaf(WT, V2.w, acc2.w); \
        acc3.x = fmaf(WT, V3.x, acc3.x); acc3.y = fmaf(WT, V3.y, acc3.y); \
        acc3.z = fmaf(WT, V3.z, acc3.z); acc3.w = fmaf(WT, V3.w, acc3.w);

    int m = 0;
    for (; m + 2 <= nnz; m += 2) {
        int2 cwa = scw[m], cwb = scw[m + 1];
        float4 a0, a1, a2, a3, b0, b1, b2, b3;
        float wa, wb;
        LOADC(cwa, a0, a1, a2, a3, wa)
        LOADC(cwb, b0, b1, b2, b3, wb)
        ACC4(a0, a1, a2, a3, wa)
        ACC4(b0, b1, b2, b3, wb)
    }
    if (m < nnz) {
        int2 cwa = scw[m];
        float4 a0, a1, a2, a3;
        float wa;
        LOADC(cwa, a0, a1, a2, a3, wa)
        ACC4(a0, a1, a2, a3, wa)
    }

    *reinterpret_cast<float4*>(obase + (hbase)      * PATCH + w0) = acc0;
    *reinterpret_cast<float4*>(obase + (hbase + 8)  * PATCH + w0) = acc1;
    *reinterpret_cast<float4*>(obase + (hbase + 16) * PATCH + w0) = acc2;
    *reinterpret_cast<float4*>(obase + (hbase + 24) * PATCH + w0) = acc3;
}

// ------------------------- launch ----------------------------------------------
extern "C" void kernel_launch(void* const* d_in, const int* in_sizes, int n_in,
                              void* d_out, int out_size) {
    const float* x_high = (const float*)d_in[0];
    const float* scores = (const float*)d_in[1];
    if (n_in >= 2 && in_sizes[0] < in_sizes[1]) {
        x_high = (const float*)d_in[1];
        scores = (const float*)d_in[0];
    }
    float* out = (float*)d_out;
    float* entr_out = out + (out_size > PATCH_ELEMS ? PATCH_ELEMS : out_size - 1);

    k1_prep<<<1, 256>>>(scores, entr_out);
    k2_topk<<<NSAMP, 256>>>();              // 500 blocks, warp-per-sample
    k3_compact<<<B * KTOP, 256>>>();
    dim3 g4(B * KTOP, 12);
    k4_patches<<<g4, 256>>>(x_high, out);
}

// round 5
// speedup vs baseline: 1.2602x; 1.2602x over previous
#include <cuda_runtime.h>
#include <stdint.h>

// Problem constants
#define B        8
#define D        256          // 16x16 score grid
#define NSAMP    500
#define KTOP     10
#define SCALE    64
#define PATCH    128
#define IMGH     1024
#define IMGW     1024
#define PATCH_ELEMS (B * KTOP * 3 * PATCH * PATCH)  // 3,932,160

// ------------------------- scratch (static, no allocs) -------------------------
__device__ float g_norm[B * D];
__device__ int   g_count[B * KTOP * D];

// ------------------------- threefry2x32 (JAX key(1) = {0,1}) -------------------
__device__ __forceinline__ uint32_t rotl32(uint32_t v, int r) {
    return (v << r) | (v >> (32 - r));
}
__device__ __forceinline__ void tf_round(uint32_t& x0, uint32_t& x1, int r) {
    x0 += x1; x1 = rotl32(x1, r); x1 ^= x0;
}
__device__ __forceinline__ void threefry2x32(uint32_t c0, uint32_t c1,
                                             uint32_t& o0, uint32_t& o1) {
    const uint32_t ks0 = 0u, ks1 = 1u, ks2 = 0x1BD11BDAu ^ ks0 ^ ks1;
    uint32_t x0 = c0 + ks0, x1 = c1 + ks1;
    tf_round(x0, x1, 13); tf_round(x0, x1, 15); tf_round(x0, x1, 26); tf_round(x0, x1, 6);
    x0 += ks1; x1 += ks2 + 1u;
    tf_round(x0, x1, 17); tf_round(x0, x1, 29); tf_round(x0, x1, 16); tf_round(x0, x1, 24);
    x0 += ks2; x1 += ks0 + 2u;
    tf_round(x0, x1, 13); tf_round(x0, x1, 15); tf_round(x0, x1, 26); tf_round(x0, x1, 6);
    x0 += ks0; x1 += ks1 + 3u;
    tf_round(x0, x1, 17); tf_round(x0, x1, 29); tf_round(x0, x1, 16); tf_round(x0, x1, 24);
    x0 += ks1; x1 += ks2 + 4u;
    tf_round(x0, x1, 13); tf_round(x0, x1, 15); tf_round(x0, x1, 26); tf_round(x0, x1, 6);
    x0 += ks2; x1 += ks0 + 5u;
    o0 = x0; o1 = x1;
}

// XLA ErfInv32 (Giles) — exact coefficients XLA emits for lax.erf_inv on f32
__device__ __forceinline__ float erfinv_xla(float x) {
    float w = -log1pf(-__fmul_rn(x, x));
    float p;
    if (w < 5.0f) {
        w = w - 2.5f;
        p = 2.81022636e-08f;
        p = fmaf(p, w, 3.43273939e-07f);
        p = fmaf(p, w, -3.5233877e-06f);
        p = fmaf(p, w, -4.39150654e-06f);
        p = fmaf(p, w, 0.00021858087f);
        p = fmaf(p, w, -0.00125372503f);
        p = fmaf(p, w, -0.00417768164f);
        p = fmaf(p, w, 0.246640727f);
        p = fmaf(p, w, 1.50140941f);
    } else {
        w = sqrtf(w) - 3.0f;
        p = -0.000200214257f;
        p = fmaf(p, w, 0.000100950558f);
        p = fmaf(p, w, 0.00134934322f);
        p = fmaf(p, w, -0.00367342844f);
        p = fmaf(p, w, 0.00573950773f);
        p = fmaf(p, w, -0.0076224613f);
        p = fmaf(p, w, 0.00943887047f);
        p = fmaf(p, w, 1.00167406f);
        p = fmaf(p, w, 2.83297682f);
    }
    return __fmul_rn(p, x);
}

// noise[e] exactly as jax.random.normal(key(1), (8,500,256), f32) with
// jax_threefry_partitionable=True: counter=(0,e), bits = o0 ^ o1
__device__ __forceinline__ float jax_normal(uint32_t e) {
    uint32_t o0, o1;
    threefry2x32(0u, e, o0, o1);
    uint32_t bits = o0 ^ o1;
    float u = __uint_as_float((bits >> 9) | 0x3f800000u) - 1.0f;  // [0,1)
    const float lo = -0.99999994f;            // nextafter(-1,0) in f32
    const float span = 2.0f;                  // f32(1.0 - lo)
    float v = fmaxf(lo, __fadd_rn(__fmul_rn(u, span), lo));
    return __fmul_rn(1.41421354f /* f32(sqrt(2)) */, erfinv_xla(v));
}

// ------------------------- kernel 1: entropy + normalize + zero counts ---------
__global__ void k1_prep(const float* __restrict__ scores, float* __restrict__ entr_out) {
    int tid = threadIdx.x;
    for (int i = tid; i < B * KTOP * D; i += 256) g_count[i] = 0;

    int w = tid >> 5;        // warp = batch
    int lane = tid & 31;
    const float* s = scores + w * D;

    float v[8];
    float mx = -3.0e38f, mn = 3.0e38f;
    #pragma unroll
    for (int q = 0; q < 8; q++) {
        v[q] = s[lane + q * 32];
        mx = fmaxf(mx, v[q]);
        mn = fminf(mn, v[q]);
    }
    #pragma unroll
    for (int o = 16; o; o >>= 1) {
        mx = fmaxf(mx, __shfl_xor_sync(0xffffffffu, mx, o));
        mn = fminf(mn, __shfl_xor_sync(0xffffffffu, mn, o));
    }
    float sumexp = 0.f;
    #pragma unroll
    for (int q = 0; q < 8; q++) sumexp += expf(v[q] - mx);
    #pragma unroll
    for (int o = 16; o; o >>= 1) sumexp += __shfl_xor_sync(0xffffffffu, sumexp, o);
    float lse = mx + logf(sumexp);

    float ent = 0.f;
    #pragma unroll
    for (int q = 0; q < 8; q++) {
        float lp = v[q] - lse;
        ent += expf(lp) * (-lp);
    }
    #pragma unroll
    for (int o = 16; o; o >>= 1) ent += __shfl_xor_sync(0xffffffffu, ent, o);

    float denom = (mx - mn) + 1e-05f;
    #pragma unroll
    for (int q = 0; q < 8; q++)
        g_norm[w * D + lane + q * 32] = __fdiv_rn(v[q] - mn, denom);

    __shared__ float sh_ent[8];
    if (lane == 0) sh_ent[w] = ent;
    __syncthreads();
    if (tid == 0) {
        float e = 0.f;
        #pragma unroll
        for (int i = 0; i < 8; i++) e += sh_ent[i];
        *entr_out = e * (1.0f / 8.0f);
    }
}

// ------------------------- kernel 2: warp-per-sample top-10 --------------------
// 500 blocks x 256 threads; each warp handles one sample, no barriers.
#define SWAPD(i, j) { if (key[i] < key[j]) { unsigned long long t = key[i]; key[i] = key[j]; key[j] = t; } }

__global__ void k2_topk() {
    int wid = threadIdx.x >> 5, lane = threadIdx.x & 31;
    int bs = blockIdx.x * 8 + wid;          // 0..3999
    int b = bs / NSAMP;

    unsigned long long key[8];
    #pragma unroll
    for (int q = 0; q < 8; q++) {
        int j = q * 32 + lane;
        float noise = jax_normal((uint32_t)bs * D + (uint32_t)j);
        float pert = __fadd_rn(g_norm[b * D + j], __fmul_rn(noise, 0.05f));
        uint32_t fb = __float_as_uint(pert);
        uint32_t ordv = fb ^ ((fb & 0x80000000u) ? 0xFFFFFFFFu : 0x80000000u);
        key[q] = ((unsigned long long)ordv << 8) | (unsigned long long)(255 - j);
    }

    // sort key[0..7] descending (19-comparator network)
    SWAPD(0,1) SWAPD(2,3) SWAPD(4,5) SWAPD(6,7)
    SWAPD(0,2) SWAPD(1,3) SWAPD(4,6) SWAPD(5,7)
    SWAPD(1,2) SWAPD(5,6)
    SWAPD(0,4) SWAPD(1,5) SWAPD(2,6) SWAPD(3,7)
    SWAPD(2,4) SWAPD(3,5)
    SWAPD(1,2) SWAPD(3,4) SWAPD(5,6)

    // 10 selection rounds; round t's winner index is kept by lane t only.
    int mine = -1;
    #pragma unroll
    for (int t = 0; t < KTOP; t++) {
        uint32_t kv = (uint32_t)(key[0] >> 8);        // ordv of my head
        uint32_t kj = (uint32_t)key[0] & 0xFFu;       // 255 - j
        uint32_t m1 = __reduce_max_sync(0xffffffffu, kv);
        uint32_t cand = (kv == m1) ? kj : 0u;
        uint32_t m2 = __reduce_max_sync(0xffffffffu, cand);
        if (lane == t) mine = 255 - (int)m2;
        if (kv == m1 && kj == m2) {                   // unique lane: pop my head
            #pragma unroll
            for (int i = 0; i < 7; i++) key[i] = key[i + 1];
            key[7] = 0ull;
        }
    }

    // ascending rank of each winner among the 10 (indices are distinct)
    int rank = 0;
    #pragma unroll
    for (int o = 0; o < KTOP; o++) {
        int other = __shfl_sync(0xffffffffu, mine, o);
        rank += (other < mine);                        // mine=-1 on lanes>=10: harmless
    }
    if (lane < KTOP)
        atomicAdd(&g_count[(b * KTOP + rank) * D + mine], 1);
}

// ------------------------- kernel 4: sparse patch gather (inline compaction) ---
// grid (80, 12): x = b*10+k, y = c*4 + rowtile(32 rows)
// block 256: lane group -> 4 w-pixels; warp id -> row base; rows r+{0,8,16,24}
__global__ void k4_patches(const float* __restrict__ x, float* __restrict__ out) {
    int bk = blockIdx.x;
    int b = bk / KTOP;
    int cz = blockIdx.y;
    int c = cz >> 2, tile = cz & 3;

    __shared__ int2 scw[D];
    __shared__ int s_cnt;
    if (threadIdx.x == 0) s_cnt = 0;
    __syncthreads();
    {
        int cval = g_count[bk * D + threadIdx.x];
        if (cval > 0) {
            int p = atomicAdd(&s_cnt, 1);
            int cell = threadIdx.x;
            int rowb = (cell >> 4) * SCALE - 32;       // [-32, 928]
            int colb = (cell & 15) * SCALE - 32;       // [-32, 928]
            scw[p] = make_int2((rowb << 16) | (colb & 0xFFFF),
                               __float_as_int((float)cval / 500.0f));
        }
    }
    __syncthreads();
    int nnz = s_cnt;

    const float* plane = x + ((size_t)(b * 3 + c) << 20);   // 1024*1024 per plane
    float* obase = out + ((size_t)(bk * 3 + c) << 14);      // 128*128 per (b,k,c)

    int w0 = (threadIdx.x & 31) * 4;        // 0..124
    int hbase = tile * 32 + (threadIdx.x >> 5);

    float4 acc0 = make_float4(0.f, 0.f, 0.f, 0.f);
    float4 acc1 = acc0, acc2 = acc0, acc3 = acc0;

    for (int m = 0; m < nnz; ++m) {
        int2 cw = scw[m];
        int rowb = cw.x >> 16;
        int colb = (cw.x << 16) >> 16;       // sign-extended
        float wt = __int_as_float(cw.y);
        int cc = colb + w0;
        bool vc = (unsigned)cc < (unsigned)IMGW;   // whole 4-chunk in/out (proved)
        int rr0 = rowb + hbase;
        #pragma unroll
        for (int hh = 0; hh < 4; hh++) {
            int rr = rr0 + hh * 8;
            if (vc && (unsigned)rr < (unsigned)IMGH) {
                float4 v = *reinterpret_cast<const float4*>(plane + rr * IMGW + cc);
                float4& acc = (hh == 0) ? acc0 : (hh == 1) ? acc1 : (hh == 2) ? acc2 : acc3;
                acc.x = fmaf(wt, v.x, acc.x);
                acc.y = fmaf(wt, v.y, acc.y);
                acc.z = fmaf(wt, v.z, acc.z);
                acc.w = fmaf(wt, v.w, acc.w);
            }
        }
    }

    #pragma unroll
    for (int hh = 0; hh < 4; hh++) {
        int h = hbase + hh * 8;
        float4 acc = (hh == 0) ? acc0 : (hh == 1) ? acc1 : (hh == 2) ? acc2 : acc3;
        *reinterpret_cast<float4*>(obase + h * PATCH + w0) = acc;
    }
}

// ------------------------- launch ----------------------------------------------
extern "C" void kernel_launch(void* const* d_in, const int* in_sizes, int n_in,
                              void* d_out, int out_size) {
    const float* x_high = (const float*)d_in[0];
    const float* scores = (const float*)d_in[1];
    if (n_in >= 2 && in_sizes[0] < in_sizes[1]) {
        x_high = (const float*)d_in[1];
        scores = (const float*)d_in[0];
    }
    float* out = (float*)d_out;
    float* entr_out = out + (out_size > PATCH_ELEMS ? PATCH_ELEMS : out_size - 1);

    k1_prep<<<1, 256>>>(scores, entr_out);
    k2_topk<<<NSAMP, 256>>>();              // 500 blocks, warp-per-sample
    dim3 g4(B * KTOP, 12);
    k4_patches<<<g4, 256>>>(x_high, out);
}

// round 6
// speedup vs baseline: 1.3478x; 1.0696x over previous
#include <cuda_runtime.h>
#include <stdint.h>

// Problem constants
#define B        8
#define D        256          // 16x16 score grid
#define NSAMP    500
#define KTOP     10
#define SCALE    64
#define PATCH    128
#define IMGH     1024
#define IMGW     1024
#define PATCH_ELEMS (B * KTOP * 3 * PATCH * PATCH)  // 3,932,160

// ------------------------- scratch (static, no allocs) -------------------------
// g_topk[k][bs] = winning cell index (byte) of rank k for sample bs. Every slot
// is written by k2, so no zeroing pass is needed.
__device__ unsigned char g_topk[KTOP * B * NSAMP];

// ------------------------- threefry2x32 (JAX key(1) = {0,1}) -------------------
__device__ __forceinline__ uint32_t rotl32(uint32_t v, int r) {
    return (v << r) | (v >> (32 - r));
}
__device__ __forceinline__ void tf_round(uint32_t& x0, uint32_t& x1, int r) {
    x0 += x1; x1 = rotl32(x1, r); x1 ^= x0;
}
__device__ __forceinline__ void threefry2x32(uint32_t c0, uint32_t c1,
                                             uint32_t& o0, uint32_t& o1) {
    const uint32_t ks0 = 0u, ks1 = 1u, ks2 = 0x1BD11BDAu ^ ks0 ^ ks1;
    uint32_t x0 = c0 + ks0, x1 = c1 + ks1;
    tf_round(x0, x1, 13); tf_round(x0, x1, 15); tf_round(x0, x1, 26); tf_round(x0, x1, 6);
    x0 += ks1; x1 += ks2 + 1u;
    tf_round(x0, x1, 17); tf_round(x0, x1, 29); tf_round(x0, x1, 16); tf_round(x0, x1, 24);
    x0 += ks2; x1 += ks0 + 2u;
    tf_round(x0, x1, 13); tf_round(x0, x1, 15); tf_round(x0, x1, 26); tf_round(x0, x1, 6);
    x0 += ks0; x1 += ks1 + 3u;
    tf_round(x0, x1, 17); tf_round(x0, x1, 29); tf_round(x0, x1, 16); tf_round(x0, x1, 24);
    x0 += ks1; x1 += ks2 + 4u;
    tf_round(x0, x1, 13); tf_round(x0, x1, 15); tf_round(x0, x1, 26); tf_round(x0, x1, 6);
    x0 += ks2; x1 += ks0 + 5u;
    o0 = x0; o1 = x1;
}

// XLA ErfInv32 (Giles) — exact coefficients XLA emits for lax.erf_inv on f32
__device__ __forceinline__ float erfinv_xla(float x) {
    float w = -log1pf(-__fmul_rn(x, x));
    float p;
    if (w < 5.0f) {
        w = w - 2.5f;
        p = 2.81022636e-08f;
        p = fmaf(p, w, 3.43273939e-07f);
        p = fmaf(p, w, -3.5233877e-06f);
        p = fmaf(p, w, -4.39150654e-06f);
        p = fmaf(p, w, 0.00021858087f);
        p = fmaf(p, w, -0.00125372503f);
        p = fmaf(p, w, -0.00417768164f);
        p = fmaf(p, w, 0.246640727f);
        p = fmaf(p, w, 1.50140941f);
    } else {
        w = sqrtf(w) - 3.0f;
        p = -0.000200214257f;
        p = fmaf(p, w, 0.000100950558f);
        p = fmaf(p, w, 0.00134934322f);
        p = fmaf(p, w, -0.00367342844f);
        p = fmaf(p, w, 0.00573950773f);
        p = fmaf(p, w, -0.0076224613f);
        p = fmaf(p, w, 0.00943887047f);
        p = fmaf(p, w, 1.00167406f);
        p = fmaf(p, w, 2.83297682f);
    }
    return __fmul_rn(p, x);
}

// noise[e] exactly as jax.random.normal(key(1), (8,500,256), f32) with
// jax_threefry_partitionable=True: counter=(0,e), bits = o0 ^ o1
__device__ __forceinline__ float jax_normal(uint32_t e) {
    uint32_t o0, o1;
    threefry2x32(0u, e, o0, o1);
    uint32_t bits = o0 ^ o1;
    float u = __uint_as_float((bits >> 9) | 0x3f800000u) - 1.0f;  // [0,1)
    const float lo = -0.99999994f;            // nextafter(-1,0) in f32
    const float span = 2.0f;                  // f32(1.0 - lo)
    float v = fmaxf(lo, __fadd_rn(__fmul_rn(u, span), lo));
    return __fmul_rn(1.41421354f /* f32(sqrt(2)) */, erfinv_xla(v));
}

// ------------------------- kernel 2: warp-per-sample top-10 --------------------
// 500 blocks x 256 threads; each warp handles one sample. Normalization is
// computed inline per warp (scores are tiny and cache-resident). Block 0 also
// computes the entropy scalar.
#define SWAPD(i, j) { if (key[i] < key[j]) { unsigned long long t = key[i]; key[i] = key[j]; key[j] = t; } }

__global__ void k2_topk(const float* __restrict__ scores, float* __restrict__ entr_out) {
    int wid = threadIdx.x >> 5, lane = threadIdx.x & 31;
    int bs = blockIdx.x * 8 + wid;          // 0..3999
    int b = bs / NSAMP;

    // inline normalization for batch b (bit-identical to previous g_norm)
    const float* s = scores + b * D;
    float v[8];
    float mx = -3.0e38f, mn = 3.0e38f;
    #pragma unroll
    for (int q = 0; q < 8; q++) {
        v[q] = s[q * 32 + lane];
        mx = fmaxf(mx, v[q]);
        mn = fminf(mn, v[q]);
    }
    #pragma unroll
    for (int o = 16; o; o >>= 1) {
        mx = fmaxf(mx, __shfl_xor_sync(0xffffffffu, mx, o));
        mn = fminf(mn, __shfl_xor_sync(0xffffffffu, mn, o));
    }
    float denom = (mx - mn) + 1e-05f;

    unsigned long long key[8];
    #pragma unroll
    for (int q = 0; q < 8; q++) {
        int j = q * 32 + lane;
        float nrm = __fdiv_rn(v[q] - mn, denom);
        float noise = jax_normal((uint32_t)bs * D + (uint32_t)j);
        float pert = __fadd_rn(nrm, __fmul_rn(noise, 0.05f));
        uint32_t fb = __float_as_uint(pert);
        uint32_t ordv = fb ^ ((fb & 0x80000000u) ? 0xFFFFFFFFu : 0x80000000u);
        key[q] = ((unsigned long long)ordv << 8) | (unsigned long long)(255 - j);
    }

    // sort key[0..7] descending (19-comparator network)
    SWAPD(0,1) SWAPD(2,3) SWAPD(4,5) SWAPD(6,7)
    SWAPD(0,2) SWAPD(1,3) SWAPD(4,6) SWAPD(5,7)
    SWAPD(1,2) SWAPD(5,6)
    SWAPD(0,4) SWAPD(1,5) SWAPD(2,6) SWAPD(3,7)
    SWAPD(2,4) SWAPD(3,5)
    SWAPD(1,2) SWAPD(3,4) SWAPD(5,6)

    // 10 selection rounds; round t's winner index is kept by lane t only.
    int mine = -1;
    #pragma unroll
    for (int t = 0; t < KTOP; t++) {
        uint32_t kv = (uint32_t)(key[0] >> 8);        // ordv of my head
        uint32_t kj = (uint32_t)key[0] & 0xFFu;       // 255 - j
        uint32_t m1 = __reduce_max_sync(0xffffffffu, kv);
        uint32_t cand = (kv == m1) ? kj : 0u;
        uint32_t m2 = __reduce_max_sync(0xffffffffu, cand);
        if (lane == t) mine = 255 - (int)m2;
        if (kv == m1 && kj == m2) {                   // unique lane: pop my head
            #pragma unroll
            for (int i = 0; i < 7; i++) key[i] = key[i + 1];
            key[7] = 0ull;
        }
    }

    // ascending rank of each winner among the 10 (indices are distinct)
    int rank = 0;
    #pragma unroll
    for (int o = 0; o < KTOP; o++) {
        int other = __shfl_sync(0xffffffffu, mine, o);
        rank += (other < mine);                        // mine=-1 on lanes>=10: harmless
    }
    if (lane < KTOP)
        g_topk[rank * (B * NSAMP) + bs] = (unsigned char)mine;

    // block 0 additionally computes the entropy scalar (warp w -> batch w)
    if (blockIdx.x == 0) {
        const float* se = scores + wid * D;
        float ev[8];
        float emx = -3.0e38f;
        #pragma unroll
        for (int q = 0; q < 8; q++) {
            ev[q] = se[q * 32 + lane];
            emx = fmaxf(emx, ev[q]);
        }
        #pragma unroll
        for (int o = 16; o; o >>= 1)
            emx = fmaxf(emx, __shfl_xor_sync(0xffffffffu, emx, o));
        float sumexp = 0.f;
        #pragma unroll
        for (int q = 0; q < 8; q++) sumexp += expf(ev[q] - emx);
        #pragma unroll
        for (int o = 16; o; o >>= 1) sumexp += __shfl_xor_sync(0xffffffffu, sumexp, o);
        float lse = emx + logf(sumexp);
        float ent = 0.f;
        #pragma unroll
        for (int q = 0; q < 8; q++) {
            float lp = ev[q] - lse;
            ent += expf(lp) * (-lp);
        }
        #pragma unroll
        for (int o = 16; o; o >>= 1) ent += __shfl_xor_sync(0xffffffffu, ent, o);

        __shared__ float sh_ent[8];
        if (lane == 0) sh_ent[wid] = ent;
        __syncthreads();
        if (threadIdx.x == 0) {
            float e = 0.f;
            #pragma unroll
            for (int i = 0; i < 8; i++) e += sh_ent[i];
            *entr_out = e * (1.0f / 8.0f);
        }
    }
}

// ------------------------- kernel 4: histogram + sparse patch gather -----------
// grid (80, 24): x = b*10+k, y = c*8 + rowtile(16 rows)
// block 256: lane group -> 4 w-pixels; warp id -> row base; rows r+{0,8}
__global__ void k4_patches(const float* __restrict__ x, float* __restrict__ out) {
    int bk = blockIdx.x;
    int b = bk / KTOP, kk = bk % KTOP;
    int cz = blockIdx.y;
    int c = cz >> 3, tile = cz & 7;

    __shared__ int  s_hist[D];
    __shared__ int2 scw[D];
    __shared__ int  s_cnt;
    s_hist[threadIdx.x] = 0;
    if (threadIdx.x == 0) s_cnt = 0;
    __syncthreads();

    // histogram the 500 winner bytes for this (b, kk)
    {
        const uint32_t* p32 = (const uint32_t*)(g_topk + kk * (B * NSAMP) + b * NSAMP);
        if (threadIdx.x < NSAMP / 4) {
            uint32_t w4 = p32[threadIdx.x];
            atomicAdd(&s_hist[w4 & 255u], 1);
            atomicAdd(&s_hist[(w4 >> 8) & 255u], 1);
            atomicAdd(&s_hist[(w4 >> 16) & 255u], 1);
            atomicAdd(&s_hist[w4 >> 24], 1);
        }
    }
    __syncthreads();
    {
        int cval = s_hist[threadIdx.x];
        if (cval > 0) {
            int p = atomicAdd(&s_cnt, 1);
            int cell = threadIdx.x;
            int rowb = (cell >> 4) * SCALE - 32;       // [-32, 928]
            int colb = (cell & 15) * SCALE - 32;       // [-32, 928]
            scw[p] = make_int2((rowb << 16) | (colb & 0xFFFF),
                               __float_as_int((float)cval / 500.0f));
        }
    }
    __syncthreads();
    int nnz = s_cnt;

    const float* plane = x + ((size_t)(b * 3 + c) << 20);   // 1024*1024 per plane
    float* obase = out + ((size_t)(bk * 3 + c) << 14);      // 128*128 per (b,k,c)

    int w0 = (threadIdx.x & 31) * 4;            // 0..124
    int hbase = tile * 16 + (threadIdx.x >> 5); // rows hbase, hbase+8

    float4 acc0 = make_float4(0.f, 0.f, 0.f, 0.f);
    float4 acc1 = acc0;

    for (int m = 0; m < nnz; ++m) {
        int2 cw = scw[m];
        int rowb = cw.x >> 16;
        int colb = (cw.x << 16) >> 16;       // sign-extended
        float wt = __int_as_float(cw.y);
        int cc = colb + w0;
        bool vc = (unsigned)cc < (unsigned)IMGW;   // whole 4-chunk in/out (proved)
        int rr0 = rowb + hbase;
        if (vc && (unsigned)rr0 < (unsigned)IMGH) {
            float4 v = *reinterpret_cast<const float4*>(plane + rr0 * IMGW + cc);
            acc0.x = fmaf(wt, v.x, acc0.x);
            acc0.y = fmaf(wt, v.y, acc0.y);
            acc0.z = fmaf(wt, v.z, acc0.z);
            acc0.w = fmaf(wt, v.w, acc0.w);
        }
        int rr1 = rr0 + 8;
        if (vc && (unsigned)rr1 < (unsigned)IMGH) {
            float4 v = *reinterpret_cast<const float4*>(plane + rr1 * IMGW + cc);
            acc1.x = fmaf(wt, v.x, acc1.x);
            acc1.y = fmaf(wt, v.y, acc1.y);
            acc1.z = fmaf(wt, v.z, acc1.z);
            acc1.w = fmaf(wt, v.w, acc1.w);
        }
    }

    *reinterpret_cast<float4*>(obase + hbase * PATCH + w0) = acc0;
    *reinterpret_cast<float4*>(obase + (hbase + 8) * PATCH + w0) = acc1;
}

// ------------------------- launch ----------------------------------------------
extern "C" void kernel_launch(void* const* d_in, const int* in_sizes, int n_in,
                              void* d_out, int out_size) {
    const float* x_high = (const float*)d_in[0];
    const float* scores = (const float*)d_in[1];
    if (n_in >= 2 && in_sizes[0] < in_sizes[1]) {
        x_high = (const float*)d_in[1];
        scores = (const float*)d_in[0];
    }
    float* out = (float*)d_out;
    float* entr_out = out + (out_size > PATCH_ELEMS ? PATCH_ELEMS : out_size - 1);

    k2_topk<<<NSAMP, 256>>>(scores, entr_out);   // 500 blocks, warp-per-sample
    dim3 g4(B * KTOP, 24);
    k4_patches<<<g4, 256>>>(x_high, out);
}